// round 17
// baseline (speedup 1.0000x reference)
#include <cuda_runtime.h>
#include <cstdint>
#include <cstring>

#define BB 16
#define NN 128
#define DD 128

#define PREP_BLOCKS 256

// Split-K GEMM config
#define SK  8
#define KB  64
#define MTILES 32          // 2048 / 64

// Scratch (device globals — allocations forbidden)
__device__ float g_xfull[BB * NN * 512];     // [hhat | deg*h | ehat | h]
__device__ float g_G[512 * 128];
__device__ float g_bb[128];
__device__ float g_deg[BB * NN];
__device__ float g_part[SK * BB * NN * 128];
__device__ int   g_cnt[MTILES];              // zero-init; self-resetting

// ---------------------------------------------------------------------------
// Fused kernel — FROZEN R7/R13 reduce (+ __ldcs on e only).
// [0,256) prep ; [256, 2304) e+h reduce.
// ---------------------------------------------------------------------------
__global__ void __launch_bounds__(256) fused_prep_reduce(
    const float* __restrict__ h,
    const float* __restrict__ adj,
    const float* __restrict__ e,
    const float* __restrict__ Wm,
    const float* __restrict__ Wu,
    const float* __restrict__ bm,
    float* __restrict__ xfull,
    float* __restrict__ deg_out,
    float* __restrict__ G,
    float* __restrict__ bb)
{
    const int tid  = threadIdx.x;
    const int lane = tid & 31;
    const int w    = tid >> 5;

    if (blockIdx.x < PREP_BLOCKS) {
        // ----------------------- prep path -----------------------
        __shared__ float s_wm[2][128];
        const int pid = blockIdx.x;
        const int c0  = pid * 2;
        const int cl  = tid >> 7;
        const int k   = tid & 127;

        {
            const int q  = tid & 127;
            const int cc = c0 + (tid >> 7);
            s_wm[tid >> 7][q] = (cc < 384) ? Wm[(size_t)q * 384 + cc] : 0.f;
        }
        __syncthreads();

        const int c = c0 + cl;
        if (c < 384) {
            const float* __restrict__ wu = Wu + (size_t)k * 256 + 128;
            float acc = 0.f;
            #pragma unroll 4
            for (int q = 0; q < 128; q += 4) {
                const float4 v = *(const float4*)(wu + q);
                acc += s_wm[cl][q]     * v.x;
                acc += s_wm[cl][q + 1] * v.y;
                acc += s_wm[cl][q + 2] * v.z;
                acc += s_wm[cl][q + 3] * v.w;
            }
            G[(size_t)c * 128 + k] = acc;
        } else {
            G[(size_t)c * 128 + k] = Wu[(size_t)k * 256 + (c - 384)];
        }

        if (pid == 0 && tid < 128) {
            const float* __restrict__ wu = Wu + (size_t)tid * 256 + 128;
            float acc = 0.f;
            #pragma unroll 4
            for (int q = 0; q < 128; q += 4) {
                const float4 v  = *(const float4*)(wu + q);
                const float4 bv = *(const float4*)(bm + q);
                acc += bv.x * v.x + bv.y * v.y + bv.z * v.z + bv.w * v.w;
            }
            bb[tid] = acc;
        }
        return;
    }

    // ----------------------- reduce path (FROZEN) -----------------------
    const int rid = blockIdx.x - PREP_BLOCKS;
    const int j = rid & (NN - 1);
    const int b = rid >> 7;

    __shared__ __align__(16) float s_re[8][DD];
    __shared__ __align__(16) float s_rh[8][DD];
    __shared__ float    s_val[NN];
    __shared__ int      s_idx[NN];
    __shared__ unsigned s_ball[4];
    __shared__ float    s_wsum[4];
    __shared__ int      s_cnt;
    __shared__ float    s_deg;

    float a = 0.f;
    if (tid < NN) {
        a = adj[((size_t)b * NN + tid) * NN + j];
        unsigned ball = __ballot_sync(0xffffffffu, a != 0.f);
        float s = a;
        #pragma unroll
        for (int off = 16; off; off >>= 1) s += __shfl_down_sync(0xffffffffu, s, off);
        if (lane == 0) { s_ball[w] = ball; s_wsum[w] = s; }
    }
    __syncthreads();
    if (tid < NN) {
        int base = 0;
        #pragma unroll
        for (int ww = 0; ww < 4; ++ww) if (ww < w) base += __popc(s_ball[ww]);
        const unsigned ball = s_ball[w];
        if (a != 0.f) {
            const int pos = base + __popc(ball & ((1u << lane) - 1u));
            s_idx[pos] = tid;
            s_val[pos] = a;
        }
        if (tid == 0) {
            s_cnt = __popc(s_ball[0]) + __popc(s_ball[1]) + __popc(s_ball[2]) + __popc(s_ball[3]);
            s_deg = s_wsum[0] + s_wsum[1] + s_wsum[2] + s_wsum[3];
        }
    }
    __syncthreads();

    const int cnt = s_cnt;
    const float deg = s_deg;

    // e[b,i,j,d]: base (i=0) = (b*NN*NN + j)*DD ; stride over i = NN*DD
    const float* __restrict__ eb = e + ((size_t)b * NN * NN + (size_t)j) * DD + lane * 4;
    const float* __restrict__ hb = h + (size_t)b * NN * DD + lane * 4;

    float4 ae = make_float4(0.f, 0.f, 0.f, 0.f);
    float4 ah = make_float4(0.f, 0.f, 0.f, 0.f);
    #pragma unroll 4
    for (int t = w; t < cnt; t += 8) {
        const float aa = s_val[t];
        const int   i  = s_idx[t];
        const float4 ev = __ldcs((const float4*)(eb + (size_t)i * (NN * DD)));  // streaming: don't thrash L2
        const float4 hv = *(const float4*)(hb + (size_t)i * DD);
        ae.x += aa * ev.x; ae.y += aa * ev.y; ae.z += aa * ev.z; ae.w += aa * ev.w;
        ah.x += aa * hv.x; ah.y += aa * hv.y; ah.z += aa * hv.z; ah.w += aa * hv.w;
    }
    *(float4*)&s_re[w][lane * 4] = ae;
    *(float4*)&s_rh[w][lane * 4] = ah;
    __syncthreads();

    if (tid < NN) {
        float se = 0.f, sh = 0.f;
        #pragma unroll
        for (int ww = 0; ww < 8; ++ww) { se += s_re[ww][tid]; sh += s_rh[ww][tid]; }
        const size_t r  = (size_t)b * NN + j;
        const float  hv = h[r * DD + tid];
        xfull[r * 512 + tid]       = sh;        // hhat
        xfull[r * 512 + 128 + tid] = deg * hv;  // deg*h
        xfull[r * 512 + 256 + tid] = se;        // ehat
        xfull[r * 512 + 384 + tid] = hv;        // h
        if (tid == 0) deg_out[r] = deg;
    }
}

// ---------------------------------------------------------------------------
// Split-K tf32 mma GEMM + integrated finish (last-block reduction).
// Grid (8, 32), 128 threads. Tile 64x128, KB=64. hi/lo compensation.
// ---------------------------------------------------------------------------
__device__ __forceinline__ float tf32hi(float x) {
    return __uint_as_float(__float_as_uint(x) & 0xffffe000u);
}

#define MMA_TF32(c, a0, a1, a2, a3, b0, b1)                                  \
    asm("mma.sync.aligned.m16n8k8.row.col.f32.tf32.tf32.f32 "                \
        "{%0,%1,%2,%3}, {%4,%5,%6,%7}, {%8,%9}, {%0,%1,%2,%3};"              \
        : "+f"((c)[0]), "+f"((c)[1]), "+f"((c)[2]), "+f"((c)[3])             \
        : "r"(a0), "r"(a1), "r"(a2), "r"(a3), "r"(b0), "r"(b1))

__global__ void __launch_bounds__(128) gemm_mma(
    const float* __restrict__ A,     // 2048 x 512 (xfull)
    const float* __restrict__ G,     // 512 x 128
    const float* __restrict__ bb,
    const float* __restrict__ bu,
    const float* __restrict__ deg,
    float* __restrict__ part,        // SK x 2048 x 128
    int* __restrict__ cnt,
    float* __restrict__ C)
{
    __shared__ __align__(16) float As_h[64][20];
    __shared__ __align__(16) float As_l[64][20];
    __shared__ __align__(16) float Bs_h[16][136];
    __shared__ __align__(16) float Bs_l[16][136];
    __shared__ int s_last;

    const int ks  = blockIdx.x;
    const int by  = blockIdx.y;
    const int m0  = by * 64;
    const int kb  = ks * KB;
    const int tid = threadIdx.x;
    const int lane = tid & 31;
    const int w    = tid >> 5;
    const int g    = lane >> 2;   // 0..7
    const int t    = lane & 3;    // 0..3

    const int am  = tid >> 1;          // 0..63
    const int ak8 = (tid & 1) * 8;     // 0, 8
    const int gk  = tid >> 4;          // 0..7 (and gk+8)
    const int gn  = (tid & 15) * 8;    // 0..120

    const float* aptr = A + (size_t)(m0 + am) * 512 + kb + ak8;
    const float* gptr = G + (size_t)(kb + gk) * 128 + gn;

    float acc[16][4];
    #pragma unroll
    for (int nt = 0; nt < 16; ++nt)
        #pragma unroll
        for (int q = 0; q < 4; ++q) acc[nt][q] = 0.f;

    float4 ra0 = *(const float4*)(aptr);
    float4 ra1 = *(const float4*)(aptr + 4);
    float4 rg00 = *(const float4*)(gptr);
    float4 rg01 = *(const float4*)(gptr + 4);
    float4 rg10 = *(const float4*)(gptr + (size_t)8 * 128);
    float4 rg11 = *(const float4*)(gptr + (size_t)8 * 128 + 4);

    #pragma unroll
    for (int s = 0; s < 4; ++s) {
        {
            float4 hi, lo;
            hi.x = tf32hi(ra0.x); lo.x = ra0.x - hi.x;
            hi.y = tf32hi(ra0.y); lo.y = ra0.y - hi.y;
            hi.z = tf32hi(ra0.z); lo.z = ra0.z - hi.z;
            hi.w = tf32hi(ra0.w); lo.w = ra0.w - hi.w;
            *(float4*)&As_h[am][ak8] = hi;
            *(float4*)&As_l[am][ak8] = lo;
            hi.x = tf32hi(ra1.x); lo.x = ra1.x - hi.x;
            hi.y = tf32hi(ra1.y); lo.y = ra1.y - hi.y;
            hi.z = tf32hi(ra1.z); lo.z = ra1.z - hi.z;
            hi.w = tf32hi(ra1.w); lo.w = ra1.w - hi.w;
            *(float4*)&As_h[am][ak8 + 4] = hi;
            *(float4*)&As_l[am][ak8 + 4] = lo;

            hi.x = tf32hi(rg00.x); lo.x = rg00.x - hi.x;
            hi.y = tf32hi(rg00.y); lo.y = rg00.y - hi.y;
            hi.z = tf32hi(rg00.z); lo.z = rg00.z - hi.z;
            hi.w = tf32hi(rg00.w); lo.w = rg00.w - hi.w;
            *(float4*)&Bs_h[gk][gn] = hi;
            *(float4*)&Bs_l[gk][gn] = lo;
            hi.x = tf32hi(rg01.x); lo.x = rg01.x - hi.x;
            hi.y = tf32hi(rg01.y); lo.y = rg01.y - hi.y;
            hi.z = tf32hi(rg01.z); lo.z = rg01.z - hi.z;
            hi.w = tf32hi(rg01.w); lo.w = rg01.w - hi.w;
            *(float4*)&Bs_h[gk][gn + 4] = hi;
            *(float4*)&Bs_l[gk][gn + 4] = lo;
            hi.x = tf32hi(rg10.x); lo.x = rg10.x - hi.x;
            hi.y = tf32hi(rg10.y); lo.y = rg10.y - hi.y;
            hi.z = tf32hi(rg10.z); lo.z = rg10.z - hi.z;
            hi.w = tf32hi(rg10.w); lo.w = rg10.w - hi.w;
            *(float4*)&Bs_h[gk + 8][gn] = hi;
            *(float4*)&Bs_l[gk + 8][gn] = lo;
            hi.x = tf32hi(rg11.x); lo.x = rg11.x - hi.x;
            hi.y = tf32hi(rg11.y); lo.y = rg11.y - hi.y;
            hi.z = tf32hi(rg11.z); lo.z = rg11.z - hi.z;
            hi.w = tf32hi(rg11.w); lo.w = rg11.w - hi.w;
            *(float4*)&Bs_h[gk + 8][gn + 4] = hi;
            *(float4*)&Bs_l[gk + 8][gn + 4] = lo;
        }
        __syncthreads();

        if (s < 3) {
            const float* ap = aptr + (s + 1) * 16;
            const float* gp = gptr + (size_t)(s + 1) * 16 * 128;
            ra0  = *(const float4*)(ap);
            ra1  = *(const float4*)(ap + 4);
            rg00 = *(const float4*)(gp);
            rg01 = *(const float4*)(gp + 4);
            rg10 = *(const float4*)(gp + (size_t)8 * 128);
            rg11 = *(const float4*)(gp + (size_t)8 * 128 + 4);
        }

        #pragma unroll
        for (int kk = 0; kk < 2; ++kk) {
            const int k0 = kk * 8;
            const int ar = w * 16 + g;
            const uint32_t ah0 = __float_as_uint(As_h[ar][k0 + t]);
            const uint32_t ah1 = __float_as_uint(As_h[ar + 8][k0 + t]);
            const uint32_t ah2 = __float_as_uint(As_h[ar][k0 + t + 4]);
            const uint32_t ah3 = __float_as_uint(As_h[ar + 8][k0 + t + 4]);
            const uint32_t al0 = __float_as_uint(As_l[ar][k0 + t]);
            const uint32_t al1 = __float_as_uint(As_l[ar + 8][k0 + t]);
            const uint32_t al2 = __float_as_uint(As_l[ar][k0 + t + 4]);
            const uint32_t al3 = __float_as_uint(As_l[ar + 8][k0 + t + 4]);
            #pragma unroll
            for (int nt = 0; nt < 16; ++nt) {
                const int n0 = nt * 8;
                const uint32_t bh0 = __float_as_uint(Bs_h[k0 + t][n0 + g]);
                const uint32_t bh1 = __float_as_uint(Bs_h[k0 + t + 4][n0 + g]);
                const uint32_t bl0 = __float_as_uint(Bs_l[k0 + t][n0 + g]);
                const uint32_t bl1 = __float_as_uint(Bs_l[k0 + t + 4][n0 + g]);
                MMA_TF32(acc[nt], ah0, ah1, ah2, ah3, bh0, bh1);
                MMA_TF32(acc[nt], ah0, ah1, ah2, ah3, bl0, bl1);
                MMA_TF32(acc[nt], al0, al1, al2, al3, bh0, bh1);
            }
        }
        __syncthreads();
    }

    // Write this split's partial tile.
    float* p = part + (size_t)ks * (BB * NN * 128);
    const int r0 = m0 + w * 16 + g;
    const int r1 = r0 + 8;
    #pragma unroll
    for (int nt = 0; nt < 16; ++nt) {
        const int col = nt * 8 + t * 2;
        *(float2*)(p + (size_t)r0 * 128 + col) = make_float2(acc[nt][0], acc[nt][1]);
        *(float2*)(p + (size_t)r1 * 128 + col) = make_float2(acc[nt][2], acc[nt][3]);
    }

    // Last block of this m-tile sums all 8 partials + bias and writes C.
    __syncthreads();
    if (tid == 0) {
        __threadfence();
        const int old = atomicAdd(&cnt[by], 1);
        s_last = (old == SK - 1);
    }
    __syncthreads();
    if (!s_last) return;

    // Clean coalesced remap: 64x128 tile = 2048 float4; 16 per thread.
    const size_t tile0 = (size_t)m0 * 128;
    #pragma unroll
    for (int q = 0; q < 16; ++q) {
        const int idx = q * 128 + tid;        // float4 index in tile
        const int row = m0 + (idx >> 5);
        const int c4  = (idx & 31) * 4;
        const size_t off = tile0 + (size_t)(idx >> 5) * 128 + c4;

        float4 s4 = make_float4(0.f, 0.f, 0.f, 0.f);
        #pragma unroll
        for (int sp = 0; sp < SK; ++sp) {
            const float4 v = *(const float4*)(part + (size_t)sp * (BB * NN * 128) + off);
            s4.x += v.x; s4.y += v.y; s4.z += v.z; s4.w += v.w;
        }
        const float dg = __ldg(deg + row);
        const float4 bbv = *(const float4*)(bb + c4);
        const float4 buv = *(const float4*)(bu + c4);
        s4.x += dg * bbv.x + buv.x;
        s4.y += dg * bbv.y + buv.y;
        s4.z += dg * bbv.z + buv.z;
        s4.w += dg * bbv.w + buv.w;
        *(float4*)(C + off) = s4;
    }

    __syncthreads();
    if (tid == 0) cnt[by] = 0;   // reset for next graph replay
}

// ---------------------------------------------------------------------------
// kernel_launch: inputs: h, adj, e, Wm, bm, Wu, bu ; output (B,N,D) fp32
// ---------------------------------------------------------------------------
extern "C" void kernel_launch(void* const* d_in, const int* in_sizes, int n_in,
                              void* d_out, int out_size)
{
    const float* h   = (const float*)d_in[0];
    const float* adj = (const float*)d_in[1];
    const float* e   = (const float*)d_in[2];
    const float* Wm  = (const float*)d_in[3];
    const float* bm  = (const float*)d_in[4];
    const float* Wu  = (const float*)d_in[5];
    const float* bu  = (const float*)d_in[6];
    float* out = (float*)d_out;

    float* xfull; cudaGetSymbolAddress((void**)&xfull, g_xfull);
    float* G;     cudaGetSymbolAddress((void**)&G,     g_G);
    float* bb;    cudaGetSymbolAddress((void**)&bb,    g_bb);
    float* deg;   cudaGetSymbolAddress((void**)&deg,   g_deg);
    float* part;  cudaGetSymbolAddress((void**)&part,  g_part);
    int*   cnt;   cudaGetSymbolAddress((void**)&cnt,   g_cnt);

    fused_prep_reduce<<<PREP_BLOCKS + BB * NN, 256>>>(
        h, adj, e, Wm, Wu, bm, xfull, deg, G, bb);

    {
        dim3 grid(SK, MTILES);   // (8, 32)
        gemm_mma<<<grid, 128>>>(xfull, G, bb, bu, deg, part, cnt, out);
    }
}